// round 2
// baseline (speedup 1.0000x reference)
#include <cuda_runtime.h>
#include <cstdint>

#define BZ 8
#define NF 10000
#define DD 16
#define HH 512
#define WW 512
#define NPIX (BZ * HH * WW)
#define HWPIX (HH * WW)

__global__ __launch_bounds__(256) void renderer_kernel(
    const float4* __restrict__ attrs,     // [BZ*NF*3*16/4] = records of 12 float4
    const float*  __restrict__ baryw,     // [BZ,H,W,3]
    const int*    __restrict__ tri,       // [BZ,H,W]
    float*        __restrict__ out)       // [BZ, D+1, H, W]
{
    int pix = blockIdx.x * blockDim.x + threadIdx.x;
    if (pix >= NPIX) return;

    int t = tri[pix];
    bool fg = (t >= 0);
    int ti = fg ? t : 0;

    // barycentric weights (3 consecutive floats)
    float w0 = baryw[pix * 3 + 0];
    float w1 = baryw[pix * 3 + 1];
    float w2 = baryw[pix * 3 + 2];
    float m = fg ? 1.0f : 0.0f;
    w0 *= m; w1 *= m; w2 *= m;

    // gather record: 3 vertices x 16 floats = 12 float4
    const float4* rec = attrs + (size_t)ti * 12;

    float acc[DD];
    #pragma unroll
    for (int q = 0; q < 4; q++) {
        float4 a0 = rec[q];       // vertex 0, channels 4q..4q+3
        float4 a1 = rec[4 + q];   // vertex 1
        float4 a2 = rec[8 + q];   // vertex 2
        acc[4*q+0] = fmaf(w0, a0.x, fmaf(w1, a1.x, w2 * a2.x));
        acc[4*q+1] = fmaf(w0, a0.y, fmaf(w1, a1.y, w2 * a2.y));
        acc[4*q+2] = fmaf(w0, a0.z, fmaf(w1, a1.z, w2 * a2.z));
        acc[4*q+3] = fmaf(w0, a0.w, fmaf(w1, a1.w, w2 * a2.w));
    }

    int n  = pix / HWPIX;
    int hw = pix - n * HWPIX;
    float* obase = out + (size_t)n * (DD + 1) * HWPIX + hw;

    #pragma unroll
    for (int d = 0; d < DD; d++)
        obase[(size_t)d * HWPIX] = acc[d];
    obase[(size_t)DD * HWPIX] = m;   // visibility channel
}

extern "C" void kernel_launch(void* const* d_in, const int* in_sizes, int n_in,
                              void* d_out, int out_size) {
    const float4* attrs = (const float4*)d_in[0];
    const float*  baryw = (const float*)d_in[1];
    const int*    tri   = (const int*)d_in[2];
    float*        out   = (float*)d_out;

    int threads = 256;
    int blocks = (NPIX + threads - 1) / threads;
    renderer_kernel<<<blocks, threads>>>(attrs, baryw, tri, out);
}

// round 4
// speedup vs baseline: 1.1473x; 1.1473x over previous
#include <cuda_runtime.h>
#include <cstdint>

#define BZ 8
#define NF 10000
#define DD 16
#define HH 512
#define WW 512
#define NPIX (BZ * HH * WW)
#define HWPIX (HH * WW)

#define TPB 256
#define RECQ 12          // float4s per record (3 verts x 16 floats)
#define RECQ_PAD 13      // padded row: 52 floats, odd multiple -> conflict-free LDS

__global__ __launch_bounds__(TPB) void renderer_kernel(
    const float4* __restrict__ attrs,     // records of 12 float4, stride 192 B
    const float*  __restrict__ baryw,     // [BZ,H,W,3]
    const int*    __restrict__ tri,       // [BZ,H,W]
    float*        __restrict__ out)       // [BZ, D+1, H, W]
{
    extern __shared__ float4 rec_s[];     // [TPB][RECQ_PAD]
    __shared__ int idx_s[TPB];

    const int tid = threadIdx.x;
    const int pix = blockIdx.x * TPB + tid;   // grid covers NPIX exactly

    // Phase 0: per-pixel metadata
    int t = tri[pix];
    bool fg = (t >= 0);
    int ti = fg ? t : 0;
    idx_s[tid] = ti;

    float w0 = baryw[pix * 3 + 0];
    float w1 = baryw[pix * 3 + 1];
    float w2 = baryw[pix * 3 + 2];
    float m = fg ? 1.0f : 0.0f;
    w0 *= m; w1 *= m; w2 *= m;

    __syncthreads();

    // Phase 1: cooperative gather. Consecutive threads fetch consecutive
    // float4s of the same record -> ~6 lines per warp-instruction instead of 32.
    #pragma unroll
    for (int it = 0; it < RECQ; it++) {
        int k = it * TPB + tid;           // 0 .. TPB*RECQ-1
        int p = k / RECQ;                 // pixel slot within block
        int q = k - p * RECQ;             // quad within record
        rec_s[p * RECQ_PAD + q] = attrs[(size_t)idx_s[p] * RECQ + q];
    }
    __syncthreads();

    // Phase 2: interpolate from smem (conflict-free via RECQ_PAD=13)
    const float4* myrec = rec_s + tid * RECQ_PAD;
    float acc[DD];
    #pragma unroll
    for (int q = 0; q < 4; q++) {
        float4 a0 = myrec[q];
        float4 a1 = myrec[4 + q];
        float4 a2 = myrec[8 + q];
        acc[4*q+0] = fmaf(w0, a0.x, fmaf(w1, a1.x, w2 * a2.x));
        acc[4*q+1] = fmaf(w0, a0.y, fmaf(w1, a1.y, w2 * a2.y));
        acc[4*q+2] = fmaf(w0, a0.z, fmaf(w1, a1.z, w2 * a2.z));
        acc[4*q+3] = fmaf(w0, a0.w, fmaf(w1, a1.w, w2 * a2.w));
    }

    // Phase 3: channel-strided coalesced stores
    int n  = pix / HWPIX;
    int hw = pix - n * HWPIX;
    float* obase = out + (size_t)n * (DD + 1) * HWPIX + hw;

    #pragma unroll
    for (int d = 0; d < DD; d++)
        obase[(size_t)d * HWPIX] = acc[d];
    obase[(size_t)DD * HWPIX] = m;   // visibility channel
}

extern "C" void kernel_launch(void* const* d_in, const int* in_sizes, int n_in,
                              void* d_out, int out_size) {
    const float4* attrs = (const float4*)d_in[0];
    const float*  baryw = (const float*)d_in[1];
    const int*    tri   = (const int*)d_in[2];
    float*        out   = (float*)d_out;

    const int smem_bytes = TPB * RECQ_PAD * sizeof(float4);  // 53,248 B
    cudaFuncSetAttribute(renderer_kernel,
                         cudaFuncAttributeMaxDynamicSharedMemorySize, smem_bytes);

    int blocks = NPIX / TPB;   // 8192, exact
    renderer_kernel<<<blocks, TPB, smem_bytes>>>(attrs, baryw, tri, out);
}